// round 1
// baseline (speedup 1.0000x reference)
#include <cuda_runtime.h>

// GCN 2-layer: h = relu(Â (x W1) + b1); out = Â (h W2) + b2
// Â = D^-1/2 (A + I) D^-1/2 with edge weights.
//
// Reassociation trick: layer-1 message is linear in x (IN=2), so we
// scatter-accumulate t[d] = Σ_e norm_e * x[src_e]  (float2, ONE red.v2/edge)
// and apply W1 + bias + relu + W2 per-node afterwards. This cuts layer-1
// atomics 8x vs scattering the 16-wide hidden activation.
//
// Self-loops (weight 1) folded analytically: deg starts at 1.0; the
// self-loop terms dinv^2 * x[i] and dinv^2 * hw[i] are added in the node
// kernels, so edge kernels only walk the E real edges.

#define NMAX 131072
#define TPB 256

__device__ float  g_dinv[NMAX];   // deg during accumulation, then dinv
__device__ float2 g_t[NMAX];      // t[d] = sum norm * x[src]  (incl. self loop)
__device__ float  g_hw[NMAX];     // hw[i] = relu(h_i) @ W2

// ---- kernel 0: deg init = 1.0 (self-loop weight) --------------------------
__global__ void k_init(int n) {
    int i = blockIdx.x * blockDim.x + threadIdx.x;
    if (i < n) g_dinv[i] = 1.0f;
}

// ---- kernel 1: deg[dst] += ew ---------------------------------------------
__global__ void k_deg(const int* __restrict__ dst,
                      const float* __restrict__ ew, int E) {
    int e = blockIdx.x * blockDim.x + threadIdx.x;
    if (e < E) atomicAdd(&g_dinv[dst[e]], ew[e]);
}

// ---- kernel 2: dinv = rsqrt(deg); t init with self-loop term ---------------
__global__ void k_node1(const float2* __restrict__ x, int n) {
    int i = blockIdx.x * blockDim.x + threadIdx.x;
    if (i >= n) return;
    float d = g_dinv[i];
    float r = (d > 0.0f) ? rsqrtf(d) : 0.0f;
    g_dinv[i] = r;
    float s = r * r;                 // self-loop norm = dinv*1*dinv
    float2 xv = x[i];
    g_t[i] = make_float2(xv.x * s, xv.y * s);
}

// ---- kernel 3: layer-1 edge scatter: t[d] += norm * x[s] -------------------
__global__ void k_edge1(const int* __restrict__ src,
                        const int* __restrict__ dst,
                        const float* __restrict__ ew,
                        const float2* __restrict__ x, int E) {
    int e = blockIdx.x * blockDim.x + threadIdx.x;
    if (e >= E) return;
    int s = src[e];
    int d = dst[e];
    const float* dinv = (const float*)g_dinv;
    float nrm = __ldg(&dinv[s]) * ew[e] * __ldg(&dinv[d]);
    float2 xv = __ldg(&x[s]);
    float a = nrm * xv.x;
    float b = nrm * xv.y;
    // one vector reduction instead of 2 scalar atomics (sm_90+)
    asm volatile("red.global.add.v2.f32 [%0], {%1, %2};"
                 :: "l"(&g_t[d]), "f"(a), "f"(b) : "memory");
}

// ---- kernel 4: per-node W1 + b1 + relu + W2; init out with self-loop -------
__global__ void k_node2(const float* __restrict__ W1,
                        const float* __restrict__ b1,
                        const float* __restrict__ W2,
                        const float* __restrict__ b2,
                        float* __restrict__ out, int n) {
    int i = blockIdx.x * blockDim.x + threadIdx.x;
    if (i >= n) return;
    float2 t = g_t[i];
    float acc = 0.0f;
#pragma unroll
    for (int k = 0; k < 16; k++) {
        float h = fmaf(t.x, __ldg(&W1[k]),
                  fmaf(t.y, __ldg(&W1[16 + k]), __ldg(&b1[k])));
        h = fmaxf(h, 0.0f);
        acc = fmaf(h, __ldg(&W2[k]), acc);
    }
    g_hw[i] = acc;
    float r = g_dinv[i];
    out[i] = __ldg(&b2[0]) + acc * r * r;   // bias + self-loop contribution
}

// ---- kernel 5: layer-2 edge scatter: out[d] += norm * hw[s] -----------------
__global__ void k_edge2(const int* __restrict__ src,
                        const int* __restrict__ dst,
                        const float* __restrict__ ew,
                        float* __restrict__ out, int E) {
    int e = blockIdx.x * blockDim.x + threadIdx.x;
    if (e >= E) return;
    int s = src[e];
    int d = dst[e];
    const float* dinv = (const float*)g_dinv;
    float nrm = __ldg(&dinv[s]) * ew[e] * __ldg(&dinv[d]);
    atomicAdd(&out[d], nrm * __ldg((const float*)&g_hw[s]));
}

extern "C" void kernel_launch(void* const* d_in, const int* in_sizes, int n_in,
                              void* d_out, int out_size) {
    const float* x  = (const float*)d_in[0];   // [N, 2]
    const int*   ei = (const int*)d_in[1];     // [2, E]
    const float* ew = (const float*)d_in[2];   // [E]
    const float* W1 = (const float*)d_in[3];   // [2, 16]
    const float* b1 = (const float*)d_in[4];   // [16]
    const float* W2 = (const float*)d_in[5];   // [16, 1]
    const float* b2 = (const float*)d_in[6];   // [1]
    float* out = (float*)d_out;                // [N, 1]

    int n = in_sizes[0] / 2;
    int E = in_sizes[2];
    const int* src = ei;
    const int* dst = ei + E;

    int nb_n = (n + TPB - 1) / TPB;
    int nb_e = (E + TPB - 1) / TPB;

    k_init <<<nb_n, TPB>>>(n);
    k_deg  <<<nb_e, TPB>>>(dst, ew, E);
    k_node1<<<nb_n, TPB>>>((const float2*)x, n);
    k_edge1<<<nb_e, TPB>>>(src, dst, ew, (const float2*)x, E);
    k_node2<<<nb_n, TPB>>>(W1, b1, W2, b2, out, n);
    k_edge2<<<nb_e, TPB>>>(src, dst, ew, out, E);
}

// round 2
// speedup vs baseline: 1.3803x; 1.3803x over previous
#include <cuda_runtime.h>

// GCN 2-layer, scatter-reassociated AND normalization-reassociated.
//
// t[d]  = dinv[d] * ( dinv[d]*x[d] + sum_e ew * dinv[s]*x[s] )
// out[d]= dinv[d] * ( dinv[d]*hw[d] + sum_e ew * dinv[s]*hw[s] ) + b2
//
// By pre-scaling node values by dinv (xd = dinv*x, hws = dinv*hw) and
// deferring the destination-side dinv[d] multiply to a node pass, each edge
// pass needs only TWO random accesses per edge (one gather + one reduction)
// instead of four. Random 4-8B accesses cost a full 32B L2 sector + an L1tex
// wavefront each, and ncu shows that is the binding resource (L2 78%, L1 85%).

#define NMAX 131072
#define TPB 256

__device__ float  g_dinv[NMAX];   // deg during accumulation, then dinv
__device__ float2 g_xd[NMAX];     // dinv[i] * x[i]          (gather source, L1)
__device__ float2 g_u[NMAX];      // scatter target layer 1  (init = xd)
__device__ float  g_hws[NMAX];    // dinv[i] * hw[i]         (gather source, L2)

// ---- kernel 0: deg init = 1.0 (self-loop weight) ---------------------------
__global__ void k_init(int n) {
    int i = blockIdx.x * blockDim.x + threadIdx.x;
    if (i < n) g_dinv[i] = 1.0f;
}

// ---- kernel 1: deg[dst] += ew ----------------------------------------------
__global__ void k_deg(const int* __restrict__ dst,
                      const float* __restrict__ ew, int E) {
    int e = blockIdx.x * blockDim.x + threadIdx.x;
    if (e < E) atomicAdd(&g_dinv[dst[e]], ew[e]);
}

// ---- kernel 2: dinv = rsqrt(deg); xd = dinv*x; u init = xd (self loop) -----
__global__ void k_node1(const float2* __restrict__ x, int n) {
    int i = blockIdx.x * blockDim.x + threadIdx.x;
    if (i >= n) return;
    float d = g_dinv[i];
    float r = (d > 0.0f) ? rsqrtf(d) : 0.0f;
    g_dinv[i] = r;
    float2 xv = x[i];
    float2 xd = make_float2(r * xv.x, r * xv.y);
    g_xd[i] = xd;
    g_u[i]  = xd;   // self-loop term: dinv[d]*1*x[d] (outer dinv applied later)
}

// ---- kernel 3: layer-1 edge scatter: u[d] += ew * xd[s] ---------------------
__global__ void k_edge1(const int* __restrict__ src,
                        const int* __restrict__ dst,
                        const float* __restrict__ ew, int E) {
    int e = blockIdx.x * blockDim.x + threadIdx.x;
    if (e >= E) return;
    int s = src[e];
    int d = dst[e];
    float w = ew[e];
    float2 xd = __ldg(&g_xd[s]);
    float a = w * xd.x;
    float b = w * xd.y;
    asm volatile("red.global.add.v2.f32 [%0], {%1, %2};"
                 :: "l"(&g_u[d]), "f"(a), "f"(b) : "memory");
}

// ---- kernel 4: t = dinv*u; MLP; hws = dinv*hw; out init = hws ---------------
__global__ void k_node2(const float* __restrict__ W1,
                        const float* __restrict__ b1,
                        const float* __restrict__ W2,
                        float* __restrict__ out, int n) {
    int i = blockIdx.x * blockDim.x + threadIdx.x;
    if (i >= n) return;
    float r = g_dinv[i];
    float2 u = g_u[i];
    float tx = r * u.x;
    float ty = r * u.y;
    float acc = 0.0f;
#pragma unroll
    for (int k = 0; k < 16; k++) {
        float h = fmaf(tx, __ldg(&W1[k]),
                  fmaf(ty, __ldg(&W1[16 + k]), __ldg(&b1[k])));
        h = fmaxf(h, 0.0f);
        acc = fmaf(h, __ldg(&W2[k]), acc);
    }
    float hws = r * acc;
    g_hws[i] = hws;
    out[i]   = hws;   // self-loop init (outer dinv + b2 applied in k_node3)
}

// ---- kernel 5: layer-2 edge scatter: out[d] += ew * hws[s] ------------------
__global__ void k_edge2(const int* __restrict__ src,
                        const int* __restrict__ dst,
                        const float* __restrict__ ew,
                        float* __restrict__ out, int E) {
    int e = blockIdx.x * blockDim.x + threadIdx.x;
    if (e >= E) return;
    int s = src[e];
    int d = dst[e];
    atomicAdd(&out[d], ew[e] * __ldg(&g_hws[s]));
}

// ---- kernel 6: out = dinv*out + b2 ------------------------------------------
__global__ void k_node3(const float* __restrict__ b2,
                        float* __restrict__ out, int n) {
    int i = blockIdx.x * blockDim.x + threadIdx.x;
    if (i >= n) return;
    out[i] = fmaf(g_dinv[i], out[i], __ldg(&b2[0]));
}

extern "C" void kernel_launch(void* const* d_in, const int* in_sizes, int n_in,
                              void* d_out, int out_size) {
    const float* x  = (const float*)d_in[0];   // [N, 2]
    const int*   ei = (const int*)d_in[1];     // [2, E]
    const float* ew = (const float*)d_in[2];   // [E]
    const float* W1 = (const float*)d_in[3];   // [2, 16]
    const float* b1 = (const float*)d_in[4];   // [16]
    const float* W2 = (const float*)d_in[5];   // [16, 1]
    const float* b2 = (const float*)d_in[6];   // [1]
    float* out = (float*)d_out;                // [N, 1]

    int n = in_sizes[0] / 2;
    int E = in_sizes[2];
    const int* src = ei;
    const int* dst = ei + E;

    int nb_n = (n + TPB - 1) / TPB;
    int nb_e = (E + TPB - 1) / TPB;

    k_init <<<nb_n, TPB>>>(n);
    k_deg  <<<nb_e, TPB>>>(dst, ew, E);
    k_node1<<<nb_n, TPB>>>((const float2*)x, n);
    k_edge1<<<nb_e, TPB>>>(src, dst, ew, E);
    k_node2<<<nb_n, TPB>>>(W1, b1, W2, out, n);
    k_edge2<<<nb_e, TPB>>>(src, dst, ew, out, E);
    k_node3<<<nb_n, TPB>>>(b2, out, n);
}